// round 1
// baseline (speedup 1.0000x reference)
#include <cuda_runtime.h>
#include <math.h>
#include <float.h>

#define BATCH 8
#define NPTS  4096
#define KN    10
#define NNB   9          // K_NEIGH - 1 neighbors kept
#define PI_F  3.14159265358979323846f

// scratch: neighbor indices (B, N, 9)
__device__ int g_knn_idx[BATCH * NPTS * NNB];

// ---------------------------------------------------------------------------
// Kernel 1: brute-force kNN, top-10 per query, matching lax.top_k stability.
// Each block: 64 queries, 4 threads per query (each scans 1024 candidates).
// SMEM: 4096 x float4 (x,y,z,|p|^2) = 64 KB, reused as merge buffer afterwards.
// ---------------------------------------------------------------------------
__global__ void __launch_bounds__(256) knn_kernel(const float* __restrict__ x)
{
    extern __shared__ float4 spts[];    // 4096 entries

    const int b    = blockIdx.x >> 6;          // 64 blocks per batch
    const int qblk = (blockIdx.x & 63) * 64;   // first query of this block
    const float* xb = x + b * 3 * NPTS;

    // load all points of this batch into shared memory
    for (int i = threadIdx.x; i < NPTS; i += blockDim.x) {
        float px = xb[i];
        float py = xb[NPTS + i];
        float pz = xb[2 * NPTS + i];
        float sq = px * px + py * py + pz * pz;
        spts[i] = make_float4(px, py, pz, sq);
    }
    __syncthreads();

    const int ql  = threadIdx.x >> 2;   // 0..63 local query
    const int sub = threadIdx.x & 3;    // candidate sub-range
    const int q   = qblk + ql;

    const float4 qp = spts[q];

    float bd[KN];
    int   bi[KN];
#pragma unroll
    for (int s = 0; s < KN; ++s) { bd[s] = __int_as_float(0x7f800000); bi[s] = 0x7fffffff; }

    const int c0 = sub * (NPTS / 4);
#pragma unroll 4
    for (int c = c0; c < c0 + NPTS / 4; ++c) {
        float4 p  = spts[c];
        float dot = qp.x * p.x + qp.y * p.y + qp.z * p.z;
        float d   = (qp.w + p.w) - 2.0f * dot;
        if (d < bd[KN - 1]) {
            bd[KN - 1] = d; bi[KN - 1] = c;
#pragma unroll
            for (int s = KN - 1; s >= 1; --s) {
                if (bd[s] < bd[s - 1]) {    // strict: stable (lower idx first on ties)
                    float td = bd[s]; bd[s] = bd[s - 1]; bd[s - 1] = td;
                    int   ti = bi[s]; bi[s] = bi[s - 1]; bi[s - 1] = ti;
                } else break;
            }
        }
    }

    // --- merge the 4 sub-lists per query (reuse SMEM) ---
    __syncthreads();
    float* md = (float*)spts;                       // 64*4*10 floats = 10 KB
    int*   mi = ((int*)spts) + 64 * 4 * KN;         // next 10 KB

    const int base = (ql * 4 + sub) * KN;
#pragma unroll
    for (int s = 0; s < KN; ++s) { md[base + s] = bd[s]; mi[base + s] = bi[s]; }
    __syncthreads();

    if (sub == 0) {
        int h0 = 0, h1 = 0, h2 = 0, h3 = 0;
        int* outp = g_knn_idx + (b * NPTS + q) * NNB;
        const int lbase = ql * 4 * KN;
#pragma unroll 1
        for (int o = 0; o < KN; ++o) {
            float best = __int_as_float(0x7f800000);
            int besti = 0x7fffffff, bs = 0;
            // stable 4-way pick: (d, idx) lexicographic
            {
                float dv = md[lbase + 0 * KN + h0]; int iv = mi[lbase + 0 * KN + h0];
                if (h0 < KN && (dv < best || (dv == best && iv < besti))) { best = dv; besti = iv; bs = 0; }
            }
            {
                float dv = md[lbase + 1 * KN + h1]; int iv = mi[lbase + 1 * KN + h1];
                if (h1 < KN && (dv < best || (dv == best && iv < besti))) { best = dv; besti = iv; bs = 1; }
            }
            {
                float dv = md[lbase + 2 * KN + h2]; int iv = mi[lbase + 2 * KN + h2];
                if (h2 < KN && (dv < best || (dv == best && iv < besti))) { best = dv; besti = iv; bs = 2; }
            }
            {
                float dv = md[lbase + 3 * KN + h3]; int iv = mi[lbase + 3 * KN + h3];
                if (h3 < KN && (dv < best || (dv == best && iv < besti))) { best = dv; besti = iv; bs = 3; }
            }
            if (bs == 0) ++h0; else if (bs == 1) ++h1; else if (bs == 2) ++h2; else ++h3;
            if (o > 0) outp[o - 1] = besti;   // drop nearest (self)
        }
    }
}

// ---------------------------------------------------------------------------
// Kernel 2: umbrella features + fused MLP (BN folded into weights) + sum over
// the 9 umbrella triangles. One thread per (b, n).
// ---------------------------------------------------------------------------
__global__ void __launch_bounds__(256) feat_kernel(
    const float* __restrict__ x,
    const float* __restrict__ conv1_w,
    const float* __restrict__ bn1_g, const float* __restrict__ bn1_b,
    const float* __restrict__ bn1_m, const float* __restrict__ bn1_v,
    const float* __restrict__ conv2_w, const float* __restrict__ conv2_b,
    const float* __restrict__ bn2_g, const float* __restrict__ bn2_b,
    const float* __restrict__ bn2_m, const float* __restrict__ bn2_v,
    const float* __restrict__ conv3_w, const float* __restrict__ conv3_b,
    float* __restrict__ out)
{
    extern __shared__ float4 spts[];    // 4096 points of this batch
    __shared__ float W1f[81], W2f[81], W3s[81];
    __shared__ float b1f[9], b2f[9], b3f[9];

    const int b  = blockIdx.x >> 4;            // 16 blocks per batch
    const int n0 = (blockIdx.x & 15) * 256;
    const int tid = threadIdx.x;

    // fold BN into conv weights
    if (tid < 81) {
        int o = tid / 9;
        float i1 = bn1_g[o] * rsqrtf(bn1_v[o] + 1e-5f);
        float i2 = bn2_g[o] * rsqrtf(bn2_v[o] + 1e-5f);
        W1f[tid] = conv1_w[tid] * i1;
        W2f[tid] = conv2_w[tid] * i2;
        W3s[tid] = conv3_w[tid];
        if (tid < 9) {
            float j1 = bn1_g[tid] * rsqrtf(bn1_v[tid] + 1e-5f);
            float j2 = bn2_g[tid] * rsqrtf(bn2_v[tid] + 1e-5f);
            b1f[tid] = bn1_b[tid] - bn1_m[tid] * j1;
            b2f[tid] = conv2_b[tid] * j2 + bn2_b[tid] - bn2_m[tid] * j2;
            b3f[tid] = conv3_b[tid];
        }
    }

    const float* xb = x + b * 3 * NPTS;
    for (int i = tid; i < NPTS; i += blockDim.x) {
        spts[i] = make_float4(xb[i], xb[NPTS + i], xb[2 * NPTS + i], 0.0f);
    }
    __syncthreads();

    const int n = n0 + tid;
    float4 p = spts[n];

    // gather neighbor offsets + sort key
    float gx[NNB], gy[NNB], gz[NNB], ph[NNB];
    const int* nb = g_knn_idx + (b * NPTS + n) * NNB;
#pragma unroll
    for (int j = 0; j < NNB; ++j) {
        float4 pp = spts[nb[j]];
        gx[j] = pp.x - p.x;
        gy[j] = pp.y - p.y;
        gz[j] = pp.z - p.z;
        ph[j] = atan2f(gy[j], gx[j]);   // monotone with reference phi
    }

    // stable insertion sort ascending by phi
#pragma unroll 1
    for (int a = 1; a < NNB; ++a) {
        float kp = ph[a], kx = gx[a], ky = gy[a], kz = gz[a];
        int t = a - 1;
        while (t >= 0 && ph[t] > kp) {
            ph[t + 1] = ph[t]; gx[t + 1] = gx[t]; gy[t + 1] = gy[t]; gz[t + 1] = gz[t];
            --t;
        }
        ph[t + 1] = kp; gx[t + 1] = kx; gy[t + 1] = ky; gz[t + 1] = kz;
    }

    float acc[9];
#pragma unroll
    for (int o = 0; o < 9; ++o) acc[o] = 0.0f;

    float pos = 1.0f;

#pragma unroll 1
    for (int j = 0; j < NNB; ++j) {
        int jn = (j + 1 == NNB) ? 0 : j + 1;
        float sx = gx[j],  sy = gy[j],  sz = gz[j];
        float rx = gx[jn], ry = gy[jn], rz = gz[jn];

        // normal = cross(s, r), normalized, sign from first triangle's x-comp
        float cxv = sy * rz - sz * ry;
        float cyv = sz * rx - sx * rz;
        float czv = sx * ry - sy * rx;
        float nrm = sqrtf(cxv * cxv + cyv * cyv + czv * czv);
        float inn = 1.0f / fmaxf(nrm, 1e-10f);
        float ux = cxv * inn, uy = cyv * inn, uz = czv * inn;
        if (j == 0) pos = (ux > 0.0f) ? 1.0f : -1.0f;  // NaN -> false -> -1 (matches jnp.where)
        float nx = ux * pos, ny = uy * pos, nz = uz * pos;
        // nan_to_num
        nx = isnan(nx) ? 0.0f : nx;
        ny = isnan(ny) ? 0.0f : ny;
        nz = isnan(nz) ? 0.0f : nz;

        // center = (0 + s + r)/3, polar
        float ccx = (sx + rx) * (1.0f / 3.0f);
        float ccy = (sy + ry) * (1.0f / 3.0f);
        float ccz = (sz + rz) * (1.0f / 3.0f);
        float rho = sqrtf(ccx * ccx + ccy * ccy + ccz * ccz);
        float ct  = ccz / fmaxf(rho, 1e-8f);
        ct = fminf(fmaxf(ct, -1.0f), 1.0f);
        float th  = acosf(ct) * (1.0f / PI_F);
        float phc = atan2f(ccy, ccx) * (1.0f / (2.0f * PI_F)) + 0.5f;

        float f[9] = { ccx, ccy, ccz, rho, th, phc, nx, ny, nz };

        float h1v[9];
#pragma unroll
        for (int o = 0; o < 9; ++o) {
            float a = b1f[o];
#pragma unroll
            for (int c = 0; c < 9; ++c) a = fmaf(W1f[o * 9 + c], f[c], a);
            h1v[o] = fmaxf(a, 0.0f);
        }
        float h2v[9];
#pragma unroll
        for (int o = 0; o < 9; ++o) {
            float a = b2f[o];
#pragma unroll
            for (int c = 0; c < 9; ++c) a = fmaf(W2f[o * 9 + c], h1v[c], a);
            h2v[o] = fmaxf(a, 0.0f);
        }
#pragma unroll
        for (int o = 0; o < 9; ++o) {
            float a = b3f[o];
#pragma unroll
            for (int c = 0; c < 9; ++c) a = fmaf(W3s[o * 9 + c], h2v[c], a);
            acc[o] += a;
        }
    }

    // out shape (B, 9, N)
    float* ob = out + b * 9 * NPTS + n;
#pragma unroll
    for (int o = 0; o < 9; ++o) ob[o * NPTS] = acc[o];
}

// ---------------------------------------------------------------------------
extern "C" void kernel_launch(void* const* d_in, const int* in_sizes, int n_in,
                              void* d_out, int out_size)
{
    const float* x       = (const float*)d_in[0];
    const float* conv1_w = (const float*)d_in[1];
    const float* bn1_g   = (const float*)d_in[2];
    const float* bn1_b   = (const float*)d_in[3];
    const float* bn1_m   = (const float*)d_in[4];
    const float* bn1_v   = (const float*)d_in[5];
    const float* conv2_w = (const float*)d_in[6];
    const float* conv2_b = (const float*)d_in[7];
    const float* bn2_g   = (const float*)d_in[8];
    const float* bn2_b   = (const float*)d_in[9];
    const float* bn2_m   = (const float*)d_in[10];
    const float* bn2_v   = (const float*)d_in[11];
    const float* conv3_w = (const float*)d_in[12];
    const float* conv3_b = (const float*)d_in[13];
    float* out = (float*)d_out;

    const int smem = NPTS * (int)sizeof(float4);   // 64 KB
    cudaFuncSetAttribute(knn_kernel,  cudaFuncAttributeMaxDynamicSharedMemorySize, smem);
    cudaFuncSetAttribute(feat_kernel, cudaFuncAttributeMaxDynamicSharedMemorySize, smem);

    knn_kernel<<<BATCH * (NPTS / 64), 256, smem>>>(x);
    feat_kernel<<<BATCH * (NPTS / 256), 256, smem>>>(
        x, conv1_w, bn1_g, bn1_b, bn1_m, bn1_v,
        conv2_w, conv2_b, bn2_g, bn2_b, bn2_m, bn2_v,
        conv3_w, conv3_b, out);
}